// round 6
// baseline (speedup 1.0000x reference)
#include <cuda_runtime.h>
#include <cuda_bf16.h>
#include <math.h>
#include <stdint.h>

// Problem constants
#define B    128
#define S    400
#define T    50
#define H    512
#define E    128
#define V    50000
#define PADN 1000
#define J3H  1536
#define CB   1537
#define VP   51000

// ---- output layout (flattened tuple, float32) ----
#define PF_OFF  ((size_t)0)
#define PG_OFF  (PF_OFF + (size_t)B*VP)
#define PV_OFF  (PG_OFF + (size_t)B)
#define AD_OFF  (PV_OFF + (size_t)B*V)
#define DH_OFF  (AD_OFF + (size_t)B*S)
#define HH_OFF  (DH_OFF + (size_t)B*(T+1)*H)
#define NPA_OFF (HH_OFF + (size_t)B*H)

// ---- device scratch ----
__device__ __align__(16) float g_gx[B * J3H];
__device__ __align__(16) float g_gh[B * J3H];
__device__ __align__(16) float g_h[B * H];
__device__ __align__(16) float g_hw[B * H];
__device__ __align__(16) float g_hwd[B * H];
__device__ __align__(16) float g_rden[B * S];          // 1/sum_t exp(previous_att)
__device__ __align__(16) float g_tu[B * S];            // unnormalized temporal
__device__ __align__(16) float g_sumT[B];
__device__ __align__(16) float g_ectx[B * H];
__device__ __align__(16) float g_dctx[B * H];
__device__ __align__(16) float g_lhb[B * E];           // logits_h [b][e]
__device__ __align__(16) float g_logits[(size_t)B * V];// holds exp(logits)
__device__ __align__(16) float g_sumexp[B];

// ============================================================
// K_denom (independent of GRU): rden[b,s] = 1/sum_t exp(pa),
// also copies previous_att into new_previous_att rows 0..T-1
// ============================================================
__global__ void k_denom(const float* __restrict__ pa, float* __restrict__ out) {
    int b = blockIdx.x, s = threadIdx.x;   // 512 threads
    if (s >= S) return;
    float d = 0.f;
    for (int t = 0; t < T; t++) {
        float v = pa[((size_t)b * T + t) * S + s];
        out[NPA_OFF + ((size_t)b * (T + 1) + t) * S + s] = v;
        d += __expf(v);
    }
    g_rden[(size_t)b * S + s] = __fdividef(1.f, d);
}

// ============================================================
// K1: fused GRU GEMMs, smem-tiled.
// ============================================================
__global__ void __launch_bounds__(256) k_grugemm(const float* __restrict__ Wih,
                                                 const float* __restrict__ Whh,
                                                 const int* __restrict__ tok,
                                                 const float* __restrict__ emb,
                                                 const float* __restrict__ lh) {
    int z = blockIdx.z;
    const float* W = z ? Whh : Wih;
    float* Cdst    = z ? g_gh : g_gx;
    int K = z ? H : E;

    __shared__ float Ws[128][33];
    __shared__ float Xs[32][17];
    __shared__ int stok[16];
    int tid = threadIdx.x;
    int j0 = blockIdx.x * 128, b0 = blockIdx.y * 16;
    if (tid < 16) stok[tid] = tok[b0 + tid];
    int tj = tid & 31, tb = tid >> 5;
    float acc[4][2];
#pragma unroll
    for (int q = 0; q < 4; q++) { acc[q][0] = 0.f; acc[q][1] = 0.f; }

    for (int kc = 0; kc < K; kc += 32) {
        __syncthreads();
#pragma unroll
        for (int q = 0; q < 4; q++) {
            int idx = tid + q * 256;
            int r = idx >> 3, c = (idx & 7) * 4;
            float4 w = *reinterpret_cast<const float4*>(W + (size_t)(j0 + r) * K + kc + c);
            Ws[r][c] = w.x; Ws[r][c + 1] = w.y; Ws[r][c + 2] = w.z; Ws[r][c + 3] = w.w;
        }
#pragma unroll
        for (int q = 0; q < 2; q++) {
            int e = tid + q * 256;
            int k = e >> 4, bb = e & 15;
            float xv;
            if (z == 0) xv = emb[(size_t)stok[bb] * E + kc + k];
            else        xv = lh[(size_t)(b0 + bb) * H + kc + k];
            Xs[k][bb] = xv;
        }
        __syncthreads();
#pragma unroll
        for (int k = 0; k < 32; k++) {
            float x0 = Xs[k][tb * 2], x1 = Xs[k][tb * 2 + 1];
#pragma unroll
            for (int q = 0; q < 4; q++) {
                float w = Ws[tj + q * 32][k];
                acc[q][0] += w * x0;
                acc[q][1] += w * x1;
            }
        }
    }
#pragma unroll
    for (int q = 0; q < 4; q++) {
        int j = j0 + tj + q * 32;
        Cdst[(size_t)(b0 + tb * 2) * J3H + j]     = acc[q][0];
        Cdst[(size_t)(b0 + tb * 2 + 1) * J3H + j] = acc[q][1];
    }
}

// ============================================================
// K2: GRU gates; zeros g_ectx / g_sumT / g_sumexp.
// ============================================================
__global__ void k_gates(const float* __restrict__ lh,
                        const float* __restrict__ b_ih,
                        const float* __restrict__ b_hh,
                        const float* __restrict__ w_h,
                        const float* __restrict__ w_d,
                        float* __restrict__ out) {
    int b = blockIdx.x >> 2;
    int i = ((blockIdx.x & 3) << 7) + threadIdx.x;
    if ((blockIdx.x & 3) == 0 && threadIdx.x == 0) {
        g_sumT[b] = 0.f;
        g_sumexp[b] = 0.f;
    }
    float gx0 = g_gx[(size_t)b * J3H + i]         + b_ih[i];
    float gh0 = g_gh[(size_t)b * J3H + i]         + b_hh[i];
    float gx1 = g_gx[(size_t)b * J3H + H + i]     + b_ih[H + i];
    float gh1 = g_gh[(size_t)b * J3H + H + i]     + b_hh[H + i];
    float gx2 = g_gx[(size_t)b * J3H + 2 * H + i] + b_ih[2 * H + i];
    float gh2 = g_gh[(size_t)b * J3H + 2 * H + i] + b_hh[2 * H + i];
    float r = 1.f / (1.f + __expf(-(gx0 + gh0)));
    float z = 1.f / (1.f + __expf(-(gx1 + gh1)));
    float n = tanhf(gx2 + r * gh2);
    float hl = lh[(size_t)b * H + i];
    float h = (1.f - z) * n + z * hl;
    g_h[(size_t)b * H + i]   = h;
    g_hw[(size_t)b * H + i]  = h * w_h[i];
    g_hwd[(size_t)b * H + i] = h * w_d[i];
    g_ectx[(size_t)b * H + i] = 0.f;
    out[HH_OFF + (size_t)b * H + i] = h;
    out[DH_OFF + ((size_t)b * (T + 1) + T) * H + i] = h;
}

// ============================================================
// K3: FUSED encoder attention — one pass over encoder_states.
// grid (5, B), 512 threads. Phase 1: 16 warps x 5 rows -> scores,
// temporal_unnorm, npa[T], partial sumT. Phase 2: re-read same
// 160KB chunk (L1/L2-hot) to accumulate unnormalized context.
// ============================================================
__global__ void __launch_bounds__(512) k_attfused(const float* __restrict__ enc,
                                                  float* __restrict__ out) {
    __shared__ float att[80];
    __shared__ float s_sum;
    int sy = blockIdx.x, b = blockIdx.y;
    int s0 = sy * 80;
    int tid = threadIdx.x, w = tid >> 5, lane = tid & 31;
    if (tid == 0) s_sum = 0.f;
    __syncthreads();

    float4 hw4[4];
    const float4* h4 = reinterpret_cast<const float4*>(g_hw + (size_t)b * H);
#pragma unroll
    for (int q = 0; q < 4; q++) hw4[q] = h4[q * 32 + lane];

    float wsum = 0.f;
#pragma unroll
    for (int i = 0; i < 5; i++) {
        int sl = w + i * 16;
        int s = s0 + sl;
        const float4* e4 = reinterpret_cast<const float4*>(enc + ((size_t)b * S + s) * H);
        float acc = 0.f;
#pragma unroll
        for (int q = 0; q < 4; q++) {
            float4 e = e4[q * 32 + lane];
            acc += e.x * hw4[q].x + e.y * hw4[q].y + e.z * hw4[q].z + e.w * hw4[q].w;
        }
        for (int o = 16; o; o >>= 1) acc += __shfl_xor_sync(0xffffffffu, acc, o);
        if (!lane) {
            out[NPA_OFF + ((size_t)b * (T + 1) + T) * S + s] = acc;
            float tu = __expf(acc) * g_rden[(size_t)b * S + s];
            g_tu[(size_t)b * S + s] = tu;
            att[sl] = tu;
            wsum += tu;
        }
    }
    if (!lane) atomicAdd(&s_sum, wsum);
    __syncthreads();
    if (tid == 0) atomicAdd(&g_sumT[b], s_sum);

    // phase 2: unnormalized context accumulation
    int h = tid;
    float a0 = 0, a1 = 0, a2 = 0, a3 = 0, a4 = 0, a5 = 0, a6 = 0, a7 = 0;
    const float* eb = enc + ((size_t)b * S + s0) * H + h;
#pragma unroll 2
    for (int s = 0; s < 80; s += 8) {
        a0 += att[s + 0] * eb[(size_t)(s + 0) * H];
        a1 += att[s + 1] * eb[(size_t)(s + 1) * H];
        a2 += att[s + 2] * eb[(size_t)(s + 2) * H];
        a3 += att[s + 3] * eb[(size_t)(s + 3) * H];
        a4 += att[s + 4] * eb[(size_t)(s + 4) * H];
        a5 += att[s + 5] * eb[(size_t)(s + 5) * H];
        a6 += att[s + 6] * eb[(size_t)(s + 6) * H];
        a7 += att[s + 7] * eb[(size_t)(s + 7) * H];
    }
    atomicAdd(&g_ectx[(size_t)b * H + h], ((a0 + a1) + (a2 + a3)) + ((a4 + a5) + (a6 + a7)));
}

// ============================================================
// K4: normalize: att_dist out + g_ectx scale. B blocks x 512.
// ============================================================
__global__ void k_attnorm(float* __restrict__ out) {
    int b = blockIdx.x, tid = threadIdx.x;
    float r = __fdividef(1.f, g_sumT[b]);
    if (tid < S) out[AD_OFF + (size_t)b * S + tid] = g_tu[(size_t)b * S + tid] * r;
    g_ectx[(size_t)b * H + tid] *= r;
}

// ============================================================
// K6: decoder attention + decoder_context + decoder_h_states copy
// ============================================================
__global__ void k_dec(const float* __restrict__ pds, float* __restrict__ out) {
    extern __shared__ float sm[];
    float* pd = sm;
    float* sc = sm + T * H;
    float* at = sc + 64;
    int b = blockIdx.x, tid = threadIdx.x;
    for (int idx = tid; idx < T * H; idx += 512) {
        float v = pds[(size_t)b * T * H + idx];
        pd[idx] = v;
        int t = idx >> 9, hh = idx & 511;
        out[DH_OFF + ((size_t)b * (T + 1) + t) * H + hh] = v;
    }
    __syncthreads();
    int w = tid >> 5, lane = tid & 31;
    for (int t = w; t < T; t += 16) {
        float acc = 0.f;
#pragma unroll
        for (int q = 0; q < 16; q++)
            acc += g_hwd[(size_t)b * H + q * 32 + lane] * pd[t * H + q * 32 + lane];
        for (int o = 16; o; o >>= 1) acc += __shfl_xor_sync(0xffffffffu, acc, o);
        if (!lane) sc[t] = acc;
    }
    __syncthreads();
    if (tid < 32) {
        float s1 = (tid < T) ? sc[tid] : -1e30f;
        float s2 = (tid + 32 < T) ? sc[tid + 32] : -1e30f;
        float m = fmaxf(s1, s2);
        for (int o = 16; o; o >>= 1) m = fmaxf(m, __shfl_xor_sync(0xffffffffu, m, o));
        float e1 = (tid < T) ? __expf(s1 - m) : 0.f;
        float e2 = (tid + 32 < T) ? __expf(s2 - m) : 0.f;
        float sum = e1 + e2;
        for (int o = 16; o; o >>= 1) sum += __shfl_xor_sync(0xffffffffu, sum, o);
        if (tid < T) at[tid] = e1 / sum;
        if (tid + 32 < T) at[tid + 32] = e2 / sum;
    }
    __syncthreads();
    float acc = 0.f;
    for (int t = 0; t < T; t++) acc += at[t] * pd[t * H + tid];
    g_dctx[(size_t)b * H + tid] = acc;
}

// ============================================================
// K8: logits_h + p_gen fused. grid (17, 4), 256 threads.
// ============================================================
__global__ void k_outh(const float* __restrict__ Wo, const float* __restrict__ bo,
                       const float* __restrict__ gw, const float* __restrict__ gb,
                       const float* __restrict__ ctrl, float* __restrict__ out) {
    if (blockIdx.x == 16) {
        int w = threadIdx.x >> 5, lane = threadIdx.x & 31;
#pragma unroll
        for (int i = 0; i < 4; i++) {
            int b = blockIdx.y * 32 + w * 4 + i;
            float acc = 0.f;
            for (int k = lane; k < H; k += 32) {
                acc += g_h[(size_t)b * H + k]    * gw[k];
                acc += g_ectx[(size_t)b * H + k] * gw[H + k];
                acc += g_dctx[(size_t)b * H + k] * gw[2 * H + k];
            }
            if (!lane) acc += ctrl[b] * gw[1536];
            for (int o = 16; o; o >>= 1) acc += __shfl_xor_sync(0xffffffffu, acc, o);
            if (!lane) out[PG_OFF + b] = 1.f / (1.f + __expf(-(acc + gb[0])));
        }
        return;
    }
    __shared__ float Ws[8 * 128];
    __shared__ float Cs[32 * 129];
    int el = threadIdx.x >> 5, bl = threadIdx.x & 31;
    int e = blockIdx.x * 8 + el, bb = blockIdx.y * 32 + bl;
    float acc = 0.f;
    for (int kc = 0; kc < 1536; kc += 128) {
        __syncthreads();
        for (int idx = threadIdx.x; idx < 1024; idx += 256) {
            int ee = idx >> 7, k = idx & 127;
            Ws[idx] = Wo[(size_t)(blockIdx.x * 8 + ee) * CB + kc + k];
        }
        const float* src = (kc < 512) ? (g_h + kc)
                         : (kc < 1024) ? (g_ectx + kc - 512)
                                       : (g_dctx + kc - 1024);
        for (int idx = threadIdx.x; idx < 4096; idx += 256) {
            int b2 = idx >> 7, k = idx & 127;
            Cs[b2 * 129 + k] = src[(size_t)(blockIdx.y * 32 + b2) * H + k];
        }
        __syncthreads();
#pragma unroll 8
        for (int k = 0; k < 128; k++)
            acc += Ws[el * 128 + k] * Cs[bl * 129 + k];
    }
    acc += Wo[(size_t)e * CB + 1536] * ctrl[bb];
    g_lhb[(size_t)bb * E + e] = acc + bo[e];
}

// ============================================================
// K10: vocab GEMM via mma.sync bf16 3-term split + bias + exp + row sums
// ============================================================
#define TSTR  132
#define TILEB (128 * TSTR * 2)
#define AHI_O 0
#define ALO_O (TILEB)
#define BHI_O (2 * TILEB)
#define BLO_O (3 * TILEB)
#define OUTV_DSMEM (4 * TILEB)

__device__ __forceinline__ void split2(float a, float b, uint32_t& hv, uint32_t& lv) {
    __nv_bfloat162 hi = __float22bfloat162_rn(make_float2(a, b));
    float ra = a - __bfloat162float(hi.x);
    float rb = b - __bfloat162float(hi.y);
    __nv_bfloat162 lo = __float22bfloat162_rn(make_float2(ra, rb));
    hv = *reinterpret_cast<uint32_t*>(&hi);
    lv = *reinterpret_cast<uint32_t*>(&lo);
}
__device__ __forceinline__ void mma16816(float* c, const uint32_t* a, const uint32_t* b) {
    asm volatile(
        "mma.sync.aligned.m16n8k16.row.col.f32.bf16.bf16.f32 "
        "{%0,%1,%2,%3}, {%4,%5,%6,%7}, {%8,%9}, {%0,%1,%2,%3};"
        : "+f"(c[0]), "+f"(c[1]), "+f"(c[2]), "+f"(c[3])
        : "r"(a[0]), "r"(a[1]), "r"(a[2]), "r"(a[3]), "r"(b[0]), "r"(b[1]));
}

__global__ void __launch_bounds__(512, 1)
k_outv_mma(const float* __restrict__ Wv, const float* __restrict__ bv) {
    extern __shared__ char smc[];
    __shared__ float s_bv[128];
    int tid = threadIdx.x;
    int vbase = blockIdx.x * 128;

    if (tid < 128) s_bv[tid] = (vbase + tid < V) ? bv[vbase + tid] : 0.f;

#pragma unroll
    for (int q = 0; q < 8; q++) {
        int idx = tid + q * 512;
        int r = idx >> 5;
        int c = (idx & 31) * 4;
        float4 w = make_float4(0.f, 0.f, 0.f, 0.f);
        if (vbase + r < V) w = *reinterpret_cast<const float4*>(Wv + (size_t)(vbase + r) * E + c);
        uint32_t h0, l0, h1, l1;
        split2(w.x, w.y, h0, l0);
        split2(w.z, w.w, h1, l1);
        size_t off = (size_t)(r * TSTR + c) * 2;
        *reinterpret_cast<uint2*>(smc + BHI_O + off) = make_uint2(h0, h1);
        *reinterpret_cast<uint2*>(smc + BLO_O + off) = make_uint2(l0, l1);
        float4 x = *reinterpret_cast<const float4*>(g_lhb + (size_t)r * E + c);
        split2(x.x, x.y, h0, l0);
        split2(x.z, x.w, h1, l1);
        *reinterpret_cast<uint2*>(smc + AHI_O + off) = make_uint2(h0, h1);
        *reinterpret_cast<uint2*>(smc + ALO_O + off) = make_uint2(l0, l1);
    }
    __syncthreads();

    int wid = tid >> 5, lane = tid & 31;
    int wm = wid >> 2, wn = wid & 3;
    int g = lane >> 2, t = lane & 3;

    float acc[2][4][4];
#pragma unroll
    for (int mi = 0; mi < 2; mi++)
#pragma unroll
        for (int ni = 0; ni < 4; ni++)
#pragma unroll
            for (int r = 0; r < 4; r++) acc[mi][ni][r] = 0.f;

#pragma unroll
    for (int term = 0; term < 3; term++) {
        int aoff = (term == 2) ? ALO_O : AHI_O;
        int boff = (term == 1) ? BLO_O : BHI_O;
#pragma unroll
        for (int ks = 0; ks < 8; ks++) {
            int kb = ks * 16;
            uint32_t af[2][4], bf[4][2];
#pragma unroll
            for (int mi = 0; mi < 2; mi++) {
                int row = wm * 32 + mi * 16 + g;
                size_t o = (size_t)aoff + (size_t)(row * TSTR + kb + 2 * t) * 2;
                af[mi][0] = *reinterpret_cast<const uint32_t*>(smc + o);
                af[mi][1] = *reinterpret_cast<const uint32_t*>(smc + o + 8 * TSTR * 2);
                af[mi][2] = *reinterpret_cast<const uint32_t*>(smc + o + 16);
                af[mi][3] = *reinterpret_cast<const uint32_t*>(smc + o + 8 * TSTR * 2 + 16);
            }
#pragma unroll
            for (int ni = 0; ni < 4; ni++) {
                int row = wn * 32 + ni * 8 + g;
                size_t o = (size_t)boff + (size_t)(row * TSTR + kb + 2 * t) * 2;
                bf[ni][0] = *reinterpret_cast<const uint32_t*>(smc + o);
                bf[ni][1] = *reinterpret_cast<const uint32_t*>(smc + o + 16);
            }
#pragma unroll
            for (int mi = 0; mi < 2; mi++)
#pragma unroll
                for (int ni = 0; ni < 4; ni++)
                    mma16816(acc[mi][ni], af[mi], bf[ni]);
        }
    }
    __syncthreads();

    float* stage = reinterpret_cast<float*>(smc);
#pragma unroll
    for (int mi = 0; mi < 2; mi++) {
        int r0 = wm * 32 + mi * 16 + g;
#pragma unroll
        for (int ni = 0; ni < 4; ni++) {
            int n0 = wn * 32 + ni * 8 + 2 * t;
            bool v0 = (vbase + n0 < V), v1 = (vbase + n0 + 1 < V);
            float e00 = v0 ? __expf(acc[mi][ni][0] + s_bv[n0])     : 0.f;
            float e01 = v1 ? __expf(acc[mi][ni][1] + s_bv[n0 + 1]) : 0.f;
            float e10 = v0 ? __expf(acc[mi][ni][2] + s_bv[n0])     : 0.f;
            float e11 = v1 ? __expf(acc[mi][ni][3] + s_bv[n0 + 1]) : 0.f;
            stage[r0 * TSTR + n0]           = e00;
            stage[r0 * TSTR + n0 + 1]       = e01;
            stage[(r0 + 8) * TSTR + n0]     = e10;
            stage[(r0 + 8) * TSTR + n0 + 1] = e11;
        }
    }
    __syncthreads();

    if (tid < 256) {
        int row = tid >> 1, half = tid & 1;
        float lsum = 0.f;
        for (int c = half * 64; c < half * 64 + 64; c++) lsum += stage[row * TSTR + c];
        atomicAdd(&g_sumexp[row], lsum);
    }
    for (int idx = tid; idx < 128 * 128; idx += 512) {
        int b = idx >> 7, c = idx & 127;
        if (vbase + c < V) g_logits[(size_t)b * V + vbase + c] = stage[b * TSTR + c];
    }
}

// ============================================================
// K11: p_vocab, p_final (vectorized float4)
// ============================================================
__global__ void k_pfinal(float* __restrict__ out) {
    int b = blockIdx.y;
    int v = (blockIdx.x * 256 + threadIdx.x) * 4;
    if (v >= VP) return;
    float pg = out[PG_OFF + b];
    if (v < V) {
        float4 L = *reinterpret_cast<const float4*>(g_logits + (size_t)b * V + v);
        float inv = __fdividef(1.f, g_sumexp[b]);
        float4 p = make_float4(L.x * inv, L.y * inv, L.z * inv, L.w * inv);
        *reinterpret_cast<float4*>(out + PV_OFF + (size_t)b * V + v) = p;
        *reinterpret_cast<float4*>(out + PF_OFF + (size_t)b * VP + v) =
            make_float4(p.x * pg, p.y * pg, p.z * pg, p.w * pg);
    } else {
        *reinterpret_cast<float4*>(out + PF_OFF + (size_t)b * VP + v) =
            make_float4(0.f, 0.f, 0.f, 0.f);
    }
}

// ============================================================
// K12: pointer scatter
// ============================================================
__global__ void k_scatter(const int* __restrict__ fiv, float* __restrict__ out) {
    int b = blockIdx.x, s = threadIdx.x;
    if (s < S) {
        float pg = out[PG_OFF + b];
        float val = (1.f - pg) * out[AD_OFF + (size_t)b * S + s];
        int idx = fiv[(size_t)b * S + s];
        atomicAdd(&out[PF_OFF + (size_t)b * VP + idx], val);
    }
}

// ============================================================
// launch — fork/join capture-safe stream overlap (side stream is
// forked from the origin stream via event wait BEFORE its first launch)
// ============================================================
extern "C" void kernel_launch(void* const* d_in, const int* in_sizes, int n_in,
                              void* d_out, int out_size) {
    const int*   tok    = (const int*)  d_in[0];
    const float* pds    = (const float*)d_in[1];
    const float* lh     = (const float*)d_in[2];
    const float* enc    = (const float*)d_in[3];
    const int*   fiv    = (const int*)  d_in[4];
    const float* pa     = (const float*)d_in[5];
    const float* ctrl   = (const float*)d_in[6];
    const float* emb    = (const float*)d_in[7];
    const float* W_ih   = (const float*)d_in[8];
    const float* W_hh   = (const float*)d_in[9];
    const float* b_ih   = (const float*)d_in[10];
    const float* b_hh   = (const float*)d_in[11];
    const float* w_h    = (const float*)d_in[12];
    const float* w_d    = (const float*)d_in[13];
    const float* gen_W  = (const float*)d_in[14];
    const float* gen_b  = (const float*)d_in[15];
    const float* outh_W = (const float*)d_in[16];
    const float* outh_b = (const float*)d_in[17];
    const float* outv_W = (const float*)d_in[18];
    const float* outv_b = (const float*)d_in[19];
    float* out = (float*)d_out;

    const int DEC_SMEM = (T * H + 128) * sizeof(float);
    cudaFuncSetAttribute(k_dec, cudaFuncAttributeMaxDynamicSharedMemorySize, DEC_SMEM);
    cudaFuncSetAttribute(k_outv_mma, cudaFuncAttributeMaxDynamicSharedMemorySize, OUTV_DSMEM);

    cudaStream_t s1;
    cudaStreamCreateWithFlags(&s1, cudaStreamNonBlocking);
    cudaEvent_t evRoot, evDenom, evGates, evDec;
    cudaEventCreateWithFlags(&evRoot,  cudaEventDisableTiming);
    cudaEventCreateWithFlags(&evDenom, cudaEventDisableTiming);
    cudaEventCreateWithFlags(&evGates, cudaEventDisableTiming);
    cudaEventCreateWithFlags(&evDec,   cudaEventDisableTiming);

    // fork side stream from origin stream FIRST (required under graph capture)
    cudaEventRecord(evRoot, 0);
    cudaStreamWaitEvent(s1, evRoot, 0);

    // side stream: temporal denominator (independent of GRU)
    k_denom<<<B, 512, 0, s1>>>(pa, out);
    cudaEventRecord(evDenom, s1);

    // main stream: GRU
    k_grugemm<<<dim3(J3H / 128, B / 16, 2), 256>>>(W_ih, W_hh, tok, emb, lh);
    k_gates<<<4 * B, 128>>>(lh, b_ih, b_hh, w_h, w_d, out);
    cudaEventRecord(evGates, 0);

    // side stream: decoder attention
    cudaStreamWaitEvent(s1, evGates, 0);
    k_dec<<<B, 512, DEC_SMEM, s1>>>(pds, out);
    cudaEventRecord(evDec, s1);

    // main stream: fused encoder attention (one pass over enc)
    cudaStreamWaitEvent(0, evDenom, 0);
    k_attfused<<<dim3(5, B), 512>>>(enc, out);
    k_attnorm<<<B, 512>>>(out);

    // main stream: output head (+p_gen), vocab GEMM, finals
    cudaStreamWaitEvent(0, evDec, 0);
    k_outh<<<dim3(17, 4), 256>>>(outh_W, outh_b, gen_W, gen_b, ctrl, out);
    k_outv_mma<<<(V + 127) / 128, 512, OUTV_DSMEM>>>(outv_W, outv_b);
    k_pfinal<<<dim3((VP / 4 + 255) / 256, B), 256>>>(out);
    k_scatter<<<B, 512>>>(fiv, out);

    cudaEventDestroy(evRoot);
    cudaEventDestroy(evDenom);
    cudaEventDestroy(evGates);
    cudaEventDestroy(evDec);
    cudaStreamDestroy(s1);
}

// round 7
// speedup vs baseline: 1.1479x; 1.1479x over previous
#include <cuda_runtime.h>
#include <cuda_bf16.h>
#include <math.h>
#include <stdint.h>

// Problem constants
#define B    128
#define S    400
#define T    50
#define H    512
#define E    128
#define V    50000
#define PADN 1000
#define J3H  1536
#define CB   1537
#define VP   51000

// ---- output layout (flattened tuple, float32) ----
#define PF_OFF  ((size_t)0)
#define PG_OFF  (PF_OFF + (size_t)B*VP)
#define PV_OFF  (PG_OFF + (size_t)B)
#define AD_OFF  (PV_OFF + (size_t)B*V)
#define DH_OFF  (AD_OFF + (size_t)B*S)
#define HH_OFF  (DH_OFF + (size_t)B*(T+1)*H)
#define NPA_OFF (HH_OFF + (size_t)B*H)

// ---- device scratch ----
__device__ __align__(16) float g_gx[B * J3H];
__device__ __align__(16) float g_gh[B * J3H];
__device__ __align__(16) float g_h[B * H];
__device__ __align__(16) float g_hw[B * H];
__device__ __align__(16) float g_hwd[B * H];
__device__ __align__(16) float g_att_scores[B * S];
__device__ __align__(16) float g_ectx[B * H];
__device__ __align__(16) float g_dctx[B * H];
__device__ __align__(16) float g_lhb[B * E];           // logits_h [b][e]
__device__ __align__(16) float g_logits[(size_t)B * V];// holds exp(logits)
__device__ __align__(16) float g_sumexp[B];

// ---- shared mma machinery (bf16 3-term split) ----
#define TSTR  132
#define TILEB (128 * TSTR * 2)
#define AHI_O 0
#define ALO_O (TILEB)
#define BHI_O (2 * TILEB)
#define BLO_O (3 * TILEB)
#define MMA_DSMEM (4 * TILEB)

__device__ __forceinline__ void split2(float a, float b, uint32_t& hv, uint32_t& lv) {
    __nv_bfloat162 hi = __float22bfloat162_rn(make_float2(a, b));
    float ra = a - __bfloat162float(hi.x);
    float rb = b - __bfloat162float(hi.y);
    __nv_bfloat162 lo = __float22bfloat162_rn(make_float2(ra, rb));
    hv = *reinterpret_cast<uint32_t*>(&hi);
    lv = *reinterpret_cast<uint32_t*>(&lo);
}
__device__ __forceinline__ void mma16816(float* c, const uint32_t* a, const uint32_t* b) {
    asm volatile(
        "mma.sync.aligned.m16n8k16.row.col.f32.bf16.bf16.f32 "
        "{%0,%1,%2,%3}, {%4,%5,%6,%7}, {%8,%9}, {%0,%1,%2,%3};"
        : "+f"(c[0]), "+f"(c[1]), "+f"(c[2]), "+f"(c[3])
        : "r"(a[0]), "r"(a[1]), "r"(a[2]), "r"(a[3]), "r"(b[0]), "r"(b[1]));
}
// 3-term accumulate over one 128x128x128 chunk resident in smem
__device__ __forceinline__ void mma_chunk(char* smc, int wm, int wn, int g, int t,
                                          float acc[2][4][4]) {
#pragma unroll
    for (int term = 0; term < 3; term++) {
        int aoff = (term == 2) ? ALO_O : AHI_O;
        int boff = (term == 1) ? BLO_O : BHI_O;
#pragma unroll
        for (int ks = 0; ks < 8; ks++) {
            int kb = ks * 16;
            uint32_t af[2][4], bf[4][2];
#pragma unroll
            for (int mi = 0; mi < 2; mi++) {
                int row = wm * 32 + mi * 16 + g;
                size_t o = (size_t)aoff + (size_t)(row * TSTR + kb + 2 * t) * 2;
                af[mi][0] = *reinterpret_cast<const uint32_t*>(smc + o);
                af[mi][1] = *reinterpret_cast<const uint32_t*>(smc + o + 8 * TSTR * 2);
                af[mi][2] = *reinterpret_cast<const uint32_t*>(smc + o + 16);
                af[mi][3] = *reinterpret_cast<const uint32_t*>(smc + o + 8 * TSTR * 2 + 16);
            }
#pragma unroll
            for (int ni = 0; ni < 4; ni++) {
                int row = wn * 32 + ni * 8 + g;
                size_t o = (size_t)boff + (size_t)(row * TSTR + kb + 2 * t) * 2;
                bf[ni][0] = *reinterpret_cast<const uint32_t*>(smc + o);
                bf[ni][1] = *reinterpret_cast<const uint32_t*>(smc + o + 16);
            }
#pragma unroll
            for (int mi = 0; mi < 2; mi++)
#pragma unroll
                for (int ni = 0; ni < 4; ni++)
                    mma16816(acc[mi][ni], af[mi], bf[ni]);
        }
    }
}

// ============================================================
// K_precopy (side stream, no deps): pds -> decoder_h_states rows 0..T-1
// ============================================================
__global__ void k_precopy(const float* __restrict__ pds, float* __restrict__ out) {
    int i = blockIdx.x * 512 + threadIdx.x;          // float4 index
    int b = i / (T * H / 4);
    int rem = i - b * (T * H / 4);
    float4 v = reinterpret_cast<const float4*>(pds)[i];
    reinterpret_cast<float4*>(out + DH_OFF + (size_t)b * (T + 1) * H)[rem] = v;
}

// ============================================================
// K1: GRU GEMMs on tensor cores (bf16 3-term split).
// grid (12, 2): y=0 -> gx = emb[tok] @ W_ih^T (K=128)
//               y=1 -> gh = lh @ W_hh^T       (K=512)
// 512 threads, one 128b x 128j tile per block, k-chunk loop.
// ============================================================
__global__ void __launch_bounds__(512, 1)
k_grumma(const float* __restrict__ Wih, const float* __restrict__ Whh,
         const int* __restrict__ tok, const float* __restrict__ emb,
         const float* __restrict__ lh) {
    extern __shared__ char smc[];
    __shared__ int stok[128];
    int z = blockIdx.y;
    int j0 = blockIdx.x * 128;
    int tid = threadIdx.x;
    if (z == 0 && tid < 128) stok[tid] = tok[tid];
    int nchunks = z ? 4 : 1;
    int K = z ? 512 : 128;
    const float* Wz = z ? Whh : Wih;
    float* Cdst = z ? g_gh : g_gx;

    int wid = tid >> 5, lane = tid & 31;
    int wm = wid >> 2, wn = wid & 3;
    int g = lane >> 2, t = lane & 3;

    float acc[2][4][4];
#pragma unroll
    for (int mi = 0; mi < 2; mi++)
#pragma unroll
        for (int ni = 0; ni < 4; ni++)
#pragma unroll
            for (int r = 0; r < 4; r++) acc[mi][ni][r] = 0.f;

    for (int c = 0; c < nchunks; c++) {
        __syncthreads();
#pragma unroll
        for (int q = 0; q < 8; q++) {
            int idx = tid + q * 512;
            int r = idx >> 5;
            int col = (idx & 31) * 4;
            float4 w = *reinterpret_cast<const float4*>(
                Wz + (size_t)(j0 + r) * K + c * 128 + col);
            uint32_t h0, l0, h1, l1;
            split2(w.x, w.y, h0, l0);
            split2(w.z, w.w, h1, l1);
            size_t off = (size_t)(r * TSTR + col) * 2;
            *reinterpret_cast<uint2*>(smc + BHI_O + off) = make_uint2(h0, h1);
            *reinterpret_cast<uint2*>(smc + BLO_O + off) = make_uint2(l0, l1);
            float4 x;
            if (z == 0) x = *reinterpret_cast<const float4*>(emb + (size_t)stok[r] * E + col);
            else        x = *reinterpret_cast<const float4*>(lh + (size_t)r * H + c * 128 + col);
            split2(x.x, x.y, h0, l0);
            split2(x.z, x.w, h1, l1);
            *reinterpret_cast<uint2*>(smc + AHI_O + off) = make_uint2(h0, h1);
            *reinterpret_cast<uint2*>(smc + ALO_O + off) = make_uint2(l0, l1);
        }
        __syncthreads();
        mma_chunk(smc, wm, wn, g, t, acc);
    }

#pragma unroll
    for (int mi = 0; mi < 2; mi++) {
        int r0 = wm * 32 + mi * 16 + g;
#pragma unroll
        for (int ni = 0; ni < 4; ni++) {
            int j = j0 + wn * 32 + ni * 8 + 2 * t;
            Cdst[(size_t)r0 * J3H + j]           = acc[mi][ni][0];
            Cdst[(size_t)r0 * J3H + j + 1]       = acc[mi][ni][1];
            Cdst[(size_t)(r0 + 8) * J3H + j]     = acc[mi][ni][2];
            Cdst[(size_t)(r0 + 8) * J3H + j + 1] = acc[mi][ni][3];
        }
    }
}

// ============================================================
// K2: GRU gates; zeros g_ectx / g_sumexp.
// ============================================================
__global__ void k_gates(const float* __restrict__ lh,
                        const float* __restrict__ b_ih,
                        const float* __restrict__ b_hh,
                        const float* __restrict__ w_h,
                        const float* __restrict__ w_d,
                        float* __restrict__ out) {
    int b = blockIdx.x >> 2;
    int i = ((blockIdx.x & 3) << 7) + threadIdx.x;
    if ((blockIdx.x & 3) == 0 && threadIdx.x == 0) g_sumexp[b] = 0.f;
    float gx0 = g_gx[(size_t)b * J3H + i]         + b_ih[i];
    float gh0 = g_gh[(size_t)b * J3H + i]         + b_hh[i];
    float gx1 = g_gx[(size_t)b * J3H + H + i]     + b_ih[H + i];
    float gh1 = g_gh[(size_t)b * J3H + H + i]     + b_hh[H + i];
    float gx2 = g_gx[(size_t)b * J3H + 2 * H + i] + b_ih[2 * H + i];
    float gh2 = g_gh[(size_t)b * J3H + 2 * H + i] + b_hh[2 * H + i];
    float r = 1.f / (1.f + __expf(-(gx0 + gh0)));
    float z = 1.f / (1.f + __expf(-(gx1 + gh1)));
    float n = tanhf(gx2 + r * gh2);
    float hl = lh[(size_t)b * H + i];
    float h = (1.f - z) * n + z * hl;
    g_h[(size_t)b * H + i]   = h;
    g_hw[(size_t)b * H + i]  = h * w_h[i];
    g_hwd[(size_t)b * H + i] = h * w_d[i];
    g_ectx[(size_t)b * H + i] = 0.f;
    out[HH_OFF + (size_t)b * H + i] = h;
    out[DH_OFF + ((size_t)b * (T + 1) + T) * H + i] = h;
}

// ============================================================
// K3: att_scores[b,s] = sum_h hw[b,h]*enc[b,s,h]  (round-4 proven)
// ============================================================
__global__ void k_attsc(const float* __restrict__ enc) {
    int wg   = blockIdx.x * 8 + (threadIdx.x >> 5);
    int lane = threadIdx.x & 31;
    int b = wg / S, s = wg % S;
    const float4* e4 = reinterpret_cast<const float4*>(enc + ((size_t)b * S + s) * H);
    const float4* h4 = reinterpret_cast<const float4*>(g_hw + (size_t)b * H);
    float acc = 0.f;
#pragma unroll
    for (int q = 0; q < 4; q++) {
        int idx = q * 32 + lane;
        float4 e = e4[idx], hv = h4[idx];
        acc += e.x * hv.x + e.y * hv.y + e.z * hv.z + e.w * hv.w;
    }
    for (int o = 16; o; o >>= 1) acc += __shfl_xor_sync(0xffffffffu, acc, o);
    if (!lane) g_att_scores[b * S + s] = acc;
}

// ============================================================
// K4: temporal attention + att_dist + new_previous_att (round-4 proven)
// ============================================================
__global__ void k_temporal(const float* __restrict__ pa, float* __restrict__ out) {
    __shared__ float red[16];
    int b = blockIdx.x, s = threadIdx.x;
    float tmp = 0.f;
    if (s < S) {
        float denom = 0.f;
        for (int t = 0; t < T; t++) {
            float v = pa[((size_t)b * T + t) * S + s];
            out[NPA_OFF + ((size_t)b * (T + 1) + t) * S + s] = v;
            denom += __expf(v);
        }
        float asc = g_att_scores[b * S + s];
        out[NPA_OFF + ((size_t)b * (T + 1) + T) * S + s] = asc;
        tmp = __expf(asc) / denom;
    }
    float v = tmp;
    for (int o = 16; o; o >>= 1) v += __shfl_xor_sync(0xffffffffu, v, o);
    if ((threadIdx.x & 31) == 0) red[threadIdx.x >> 5] = v;
    __syncthreads();
    if (threadIdx.x < 16) {
        float r = red[threadIdx.x];
        for (int o = 8; o; o >>= 1) r += __shfl_xor_sync(0xffffu, r, o);
        if (!threadIdx.x) red[0] = r;
    }
    __syncthreads();
    if (s < S) out[AD_OFF + (size_t)b * S + s] = tmp / red[0];
}

// ============================================================
// K5: encoder_context partial: grid (5, B), 80 s-rows per block
// ============================================================
__global__ void k_ectx(const float* __restrict__ enc, const float* __restrict__ out_ro) {
    __shared__ float att[80];
    int sy = blockIdx.x, b = blockIdx.y;
    int s0 = sy * 80;
    int h = threadIdx.x;
    if (h < 80) att[h] = out_ro[AD_OFF + (size_t)b * S + s0 + h];
    __syncthreads();
    float a0 = 0, a1 = 0, a2 = 0, a3 = 0, a4 = 0, a5 = 0, a6 = 0, a7 = 0;
    const float* eb = enc + ((size_t)b * S + s0) * H + h;
    for (int s = 0; s < 80; s += 8) {
        a0 += att[s + 0] * eb[(size_t)(s + 0) * H];
        a1 += att[s + 1] * eb[(size_t)(s + 1) * H];
        a2 += att[s + 2] * eb[(size_t)(s + 2) * H];
        a3 += att[s + 3] * eb[(size_t)(s + 3) * H];
        a4 += att[s + 4] * eb[(size_t)(s + 4) * H];
        a5 += att[s + 5] * eb[(size_t)(s + 5) * H];
        a6 += att[s + 6] * eb[(size_t)(s + 6) * H];
        a7 += att[s + 7] * eb[(size_t)(s + 7) * H];
    }
    atomicAdd(&g_ectx[(size_t)b * H + h], ((a0 + a1) + (a2 + a3)) + ((a4 + a5) + (a6 + a7)));
}

// ============================================================
// K6: decoder attention (no copy — precopy handles DH rows 0..T-1)
// ============================================================
__global__ void k_dec(const float* __restrict__ pds, float* __restrict__ out) {
    extern __shared__ float sm[];
    float* pd = sm;
    float* sc = sm + T * H;
    float* at = sc + 64;
    int b = blockIdx.x, tid = threadIdx.x;
    for (int idx = tid; idx < T * H; idx += 512)
        pd[idx] = pds[(size_t)b * T * H + idx];
    __syncthreads();
    int w = tid >> 5, lane = tid & 31;
    for (int t = w; t < T; t += 16) {
        float acc = 0.f;
#pragma unroll
        for (int q = 0; q < 16; q++)
            acc += g_hwd[(size_t)b * H + q * 32 + lane] * pd[t * H + q * 32 + lane];
        for (int o = 16; o; o >>= 1) acc += __shfl_xor_sync(0xffffffffu, acc, o);
        if (!lane) sc[t] = acc;
    }
    __syncthreads();
    if (tid < 32) {
        float s1 = (tid < T) ? sc[tid] : -1e30f;
        float s2 = (tid + 32 < T) ? sc[tid + 32] : -1e30f;
        float m = fmaxf(s1, s2);
        for (int o = 16; o; o >>= 1) m = fmaxf(m, __shfl_xor_sync(0xffffffffu, m, o));
        float e1 = (tid < T) ? __expf(s1 - m) : 0.f;
        float e2 = (tid + 32 < T) ? __expf(s2 - m) : 0.f;
        float sum = e1 + e2;
        for (int o = 16; o; o >>= 1) sum += __shfl_xor_sync(0xffffffffu, sum, o);
        if (tid < T) at[tid] = e1 / sum;
        if (tid + 32 < T) at[tid + 32] = e2 / sum;
    }
    __syncthreads();
    float acc = 0.f;
    for (int t = 0; t < T; t++) acc += at[t] * pd[t * H + tid];
    g_dctx[(size_t)b * H + tid] = acc;
}

// ============================================================
// K8: logits_h + p_gen fused. grid (17, 4), 256 threads.
// ============================================================
__global__ void k_outh(const float* __restrict__ Wo, const float* __restrict__ bo,
                       const float* __restrict__ gw, const float* __restrict__ gb,
                       const float* __restrict__ ctrl, float* __restrict__ out) {
    if (blockIdx.x == 16) {
        int w = threadIdx.x >> 5, lane = threadIdx.x & 31;
#pragma unroll
        for (int i = 0; i < 4; i++) {
            int b = blockIdx.y * 32 + w * 4 + i;
            float acc = 0.f;
            for (int k = lane; k < H; k += 32) {
                acc += g_h[(size_t)b * H + k]    * gw[k];
                acc += g_ectx[(size_t)b * H + k] * gw[H + k];
                acc += g_dctx[(size_t)b * H + k] * gw[2 * H + k];
            }
            if (!lane) acc += ctrl[b] * gw[1536];
            for (int o = 16; o; o >>= 1) acc += __shfl_xor_sync(0xffffffffu, acc, o);
            if (!lane) out[PG_OFF + b] = 1.f / (1.f + __expf(-(acc + gb[0])));
        }
        return;
    }
    __shared__ float Ws[8 * 128];
    __shared__ float Cs[32 * 129];
    int el = threadIdx.x >> 5, bl = threadIdx.x & 31;
    int e = blockIdx.x * 8 + el, bb = blockIdx.y * 32 + bl;
    float acc = 0.f;
    for (int kc = 0; kc < 1536; kc += 128) {
        __syncthreads();
        for (int idx = threadIdx.x; idx < 1024; idx += 256) {
            int ee = idx >> 7, k = idx & 127;
            Ws[idx] = Wo[(size_t)(blockIdx.x * 8 + ee) * CB + kc + k];
        }
        const float* src = (kc < 512) ? (g_h + kc)
                         : (kc < 1024) ? (g_ectx + kc - 512)
                                       : (g_dctx + kc - 1024);
        for (int idx = threadIdx.x; idx < 4096; idx += 256) {
            int b2 = idx >> 7, k = idx & 127;
            Cs[b2 * 129 + k] = src[(size_t)(blockIdx.y * 32 + b2) * H + k];
        }
        __syncthreads();
#pragma unroll 8
        for (int k = 0; k < 128; k++)
            acc += Ws[el * 128 + k] * Cs[bl * 129 + k];
    }
    acc += Wo[(size_t)e * CB + 1536] * ctrl[bb];
    g_lhb[(size_t)bb * E + e] = acc + bo[e];
}

// ============================================================
// K10: vocab GEMM (mma split) + bias + exp + row sums
// ============================================================
__global__ void __launch_bounds__(512, 1)
k_outv_mma(const float* __restrict__ Wv, const float* __restrict__ bv) {
    extern __shared__ char smc[];
    __shared__ float s_bv[128];
    int tid = threadIdx.x;
    int vbase = blockIdx.x * 128;

    if (tid < 128) s_bv[tid] = (vbase + tid < V) ? bv[vbase + tid] : 0.f;

#pragma unroll
    for (int q = 0; q < 8; q++) {
        int idx = tid + q * 512;
        int r = idx >> 5;
        int c = (idx & 31) * 4;
        float4 w = make_float4(0.f, 0.f, 0.f, 0.f);
        if (vbase + r < V) w = *reinterpret_cast<const float4*>(Wv + (size_t)(vbase + r) * E + c);
        uint32_t h0, l0, h1, l1;
        split2(w.x, w.y, h0, l0);
        split2(w.z, w.w, h1, l1);
        size_t off = (size_t)(r * TSTR + c) * 2;
        *reinterpret_cast<uint2*>(smc + BHI_O + off) = make_uint2(h0, h1);
        *reinterpret_cast<uint2*>(smc + BLO_O + off) = make_uint2(l0, l1);
        float4 x = *reinterpret_cast<const float4*>(g_lhb + (size_t)r * E + c);
        split2(x.x, x.y, h0, l0);
        split2(x.z, x.w, h1, l1);
        *reinterpret_cast<uint2*>(smc + AHI_O + off) = make_uint2(h0, h1);
        *reinterpret_cast<uint2*>(smc + ALO_O + off) = make_uint2(l0, l1);
    }
    __syncthreads();

    int wid = tid >> 5, lane = tid & 31;
    int wm = wid >> 2, wn = wid & 3;
    int g = lane >> 2, t = lane & 3;

    float acc[2][4][4];
#pragma unroll
    for (int mi = 0; mi < 2; mi++)
#pragma unroll
        for (int ni = 0; ni < 4; ni++)
#pragma unroll
            for (int r = 0; r < 4; r++) acc[mi][ni][r] = 0.f;

    mma_chunk(smc, wm, wn, g, t, acc);
    __syncthreads();

    float* stage = reinterpret_cast<float*>(smc);
#pragma unroll
    for (int mi = 0; mi < 2; mi++) {
        int r0 = wm * 32 + mi * 16 + g;
#pragma unroll
        for (int ni = 0; ni < 4; ni++) {
            int n0 = wn * 32 + ni * 8 + 2 * t;
            bool v0 = (vbase + n0 < V), v1 = (vbase + n0 + 1 < V);
            float e00 = v0 ? __expf(acc[mi][ni][0] + s_bv[n0])     : 0.f;
            float e01 = v1 ? __expf(acc[mi][ni][1] + s_bv[n0 + 1]) : 0.f;
            float e10 = v0 ? __expf(acc[mi][ni][2] + s_bv[n0])     : 0.f;
            float e11 = v1 ? __expf(acc[mi][ni][3] + s_bv[n0 + 1]) : 0.f;
            stage[r0 * TSTR + n0]           = e00;
            stage[r0 * TSTR + n0 + 1]       = e01;
            stage[(r0 + 8) * TSTR + n0]     = e10;
            stage[(r0 + 8) * TSTR + n0 + 1] = e11;
        }
    }
    __syncthreads();

    if (tid < 256) {
        int row = tid >> 1, half = tid & 1;
        float lsum = 0.f;
        for (int c = half * 64; c < half * 64 + 64; c++) lsum += stage[row * TSTR + c];
        atomicAdd(&g_sumexp[row], lsum);
    }
    for (int idx = tid; idx < 128 * 128; idx += 512) {
        int b = idx >> 7, c = idx & 127;
        if (vbase + c < V) g_logits[(size_t)b * V + vbase + c] = stage[b * TSTR + c];
    }
}

// ============================================================
// K11: p_vocab, p_final (vectorized float4)
// ============================================================
__global__ void k_pfinal(float* __restrict__ out) {
    int b = blockIdx.y;
    int v = (blockIdx.x * 256 + threadIdx.x) * 4;
    if (v >= VP) return;
    float pg = out[PG_OFF + b];
    if (v < V) {
        float4 L = *reinterpret_cast<const float4*>(g_logits + (size_t)b * V + v);
        float inv = __fdividef(1.f, g_sumexp[b]);
        float4 p = make_float4(L.x * inv, L.y * inv, L.z * inv, L.w * inv);
        *reinterpret_cast<float4*>(out + PV_OFF + (size_t)b * V + v) = p;
        *reinterpret_cast<float4*>(out + PF_OFF + (size_t)b * VP + v) =
            make_float4(p.x * pg, p.y * pg, p.z * pg, p.w * pg);
    } else {
        *reinterpret_cast<float4*>(out + PF_OFF + (size_t)b * VP + v) =
            make_float4(0.f, 0.f, 0.f, 0.f);
    }
}

// ============================================================
// K12: pointer scatter
// ============================================================
__global__ void k_scatter(const int* __restrict__ fiv, float* __restrict__ out) {
    int b = blockIdx.x, s = threadIdx.x;
    if (s < S) {
        float pg = out[PG_OFF + b];
        float val = (1.f - pg) * out[AD_OFF + (size_t)b * S + s];
        int idx = fiv[(size_t)b * S + s];
        atomicAdd(&out[PF_OFF + (size_t)b * VP + idx], val);
    }
}

// ============================================================
// launch
// ============================================================
extern "C" void kernel_launch(void* const* d_in, const int* in_sizes, int n_in,
                              void* d_out, int out_size) {
    const int*   tok    = (const int*)  d_in[0];
    const float* pds    = (const float*)d_in[1];
    const float* lh     = (const float*)d_in[2];
    const float* enc    = (const float*)d_in[3];
    const int*   fiv    = (const int*)  d_in[4];
    const float* pa     = (const float*)d_in[5];
    const float* ctrl   = (const float*)d_in[6];
    const float* emb    = (const float*)d_in[7];
    const float* W_ih   = (const float*)d_in[8];
    const float* W_hh   = (const float*)d_in[9];
    const float* b_ih   = (const float*)d_in[10];
    const float* b_hh   = (const float*)d_in[11];
    const float* w_h    = (const float*)d_in[12];
    const float* w_d    = (const float*)d_in[13];
    const float* gen_W  = (const float*)d_in[14];
    const float* gen_b  = (const float*)d_in[15];
    const float* outh_W = (const float*)d_in[16];
    const float* outh_b = (const float*)d_in[17];
    const float* outv_W = (const float*)d_in[18];
    const float* outv_b = (const float*)d_in[19];
    float* out = (float*)d_out;

    const int DEC_SMEM = (T * H + 128) * sizeof(float);
    cudaFuncSetAttribute(k_dec, cudaFuncAttributeMaxDynamicSharedMemorySize, DEC_SMEM);
    cudaFuncSetAttribute(k_outv_mma, cudaFuncAttributeMaxDynamicSharedMemorySize, MMA_DSMEM);
    cudaFuncSetAttribute(k_grumma, cudaFuncAttributeMaxDynamicSharedMemorySize, MMA_DSMEM);

    cudaStream_t s1;
    cudaStreamCreateWithFlags(&s1, cudaStreamNonBlocking);
    cudaEvent_t evRoot, evGates, evDec;
    cudaEventCreateWithFlags(&evRoot,  cudaEventDisableTiming);
    cudaEventCreateWithFlags(&evGates, cudaEventDisableTiming);
    cudaEventCreateWithFlags(&evDec,   cudaEventDisableTiming);

    // fork side stream from origin stream FIRST (graph-capture requirement)
    cudaEventRecord(evRoot, 0);
    cudaStreamWaitEvent(s1, evRoot, 0);

    // side stream: pds -> decoder_h_states copy (no deps)
    k_precopy<<<(B * T * H / 4) / 512, 512, 0, s1>>>(pds, out);

    // main stream: GRU (tensor-core GEMMs)
    k_grumma<<<dim3(J3H / 128, 2), 512, MMA_DSMEM>>>(W_ih, W_hh, tok, emb, lh);
    k_gates<<<4 * B, 128>>>(lh, b_ih, b_hh, w_h, w_d, out);
    cudaEventRecord(evGates, 0);

    // side stream: decoder attention (after gates; copy already done)
    cudaStreamWaitEvent(s1, evGates, 0);
    k_dec<<<B, 512, DEC_SMEM, s1>>>(pds, out);
    cudaEventRecord(evDec, s1);

    // main stream: encoder attention chain (round-4 proven)
    k_attsc<<<(B * S) / 8, 256>>>(enc);
    k_temporal<<<B, 512>>>(pa, out);
    k_ectx<<<dim3(5, B), 512>>>(enc, out);

    // main stream: output head (+p_gen), vocab GEMM, finals
    cudaStreamWaitEvent(0, evDec, 0);
    k_outh<<<dim3(17, 4), 256>>>(outh_W, outh_b, gen_W, gen_b, ctrl, out);
    k_outv_mma<<<(V + 127) / 128, 512, MMA_DSMEM>>>(outv_W, outv_b);
    k_pfinal<<<dim3((VP / 4 + 255) / 256, B), 256>>>(out);
    k_scatter<<<B, 512>>>(fiv, out);

    cudaEventDestroy(evRoot);
    cudaEventDestroy(evGates);
    cudaEventDestroy(evDec);
    cudaStreamDestroy(s1);
}